// round 2
// baseline (speedup 1.0000x reference)
#include <cuda_runtime.h>
#include <math.h>

#define BB 2
#define TT 2048
#define HIDDEN 1024
#define NH 16
#define QKV_O 3072   // (16 + 2*16) * 64
#define MROWS (BB*TT) // 4096

// Scratch (allocation-free rule: __device__ globals)
__device__ float g_qkv[(size_t)MROWS * QKV_O];   // [B*T, 3072]
__device__ float g_ctx[(size_t)MROWS * HIDDEN];  // [B*T, 1024]

// ---------------------------------------------------------------------------
// SGEMM: C[M,N] = A[M,K] * B[N,K]^T  (row-major, K%16==0, M,N%128==0)
// ---------------------------------------------------------------------------
__global__ __launch_bounds__(256) void sgemm_nt(const float* __restrict__ A,
                                                const float* __restrict__ Bm,
                                                float* __restrict__ C,
                                                int M, int N, int K)
{
    const int BM = 128, BN = 128, BK = 16;
    __shared__ float As[16][132];
    __shared__ float Bs[16][132];
    const int tid = threadIdx.x;
    const int tx = tid & 15;
    const int ty = tid >> 4;
    const int bm = blockIdx.y * BM;
    const int bn = blockIdx.x * BN;

    float acc[8][8];
#pragma unroll
    for (int i = 0; i < 8; i++)
#pragma unroll
        for (int j = 0; j < 8; j++) acc[i][j] = 0.f;

    for (int k0 = 0; k0 < K; k0 += BK) {
#pragma unroll
        for (int i = 0; i < 2; i++) {
            int v = tid + i * 256;
            int row = v >> 2;
            int kv  = (v & 3) << 2;
            float4 a4 = *(const float4*)&A[(size_t)(bm + row) * K + k0 + kv];
            As[kv + 0][row] = a4.x; As[kv + 1][row] = a4.y;
            As[kv + 2][row] = a4.z; As[kv + 3][row] = a4.w;
            float4 b4 = *(const float4*)&Bm[(size_t)(bn + row) * K + k0 + kv];
            Bs[kv + 0][row] = b4.x; Bs[kv + 1][row] = b4.y;
            Bs[kv + 2][row] = b4.z; Bs[kv + 3][row] = b4.w;
        }
        __syncthreads();
#pragma unroll
        for (int kk = 0; kk < BK; kk++) {
            float a[8], b[8];
#pragma unroll
            for (int i = 0; i < 4; i++) {
                a[i]     = As[kk][ty * 4 + i];
                a[i + 4] = As[kk][64 + ty * 4 + i];
                b[i]     = Bs[kk][tx * 4 + i];
                b[i + 4] = Bs[kk][64 + tx * 4 + i];
            }
#pragma unroll
            for (int i = 0; i < 8; i++)
#pragma unroll
                for (int j = 0; j < 8; j++)
                    acc[i][j] += a[i] * b[j];
        }
        __syncthreads();
    }

#pragma unroll
    for (int i = 0; i < 8; i++) {
        int row = bm + ((i < 4) ? (ty * 4 + i) : (64 + ty * 4 + (i - 4)));
#pragma unroll
        for (int j = 0; j < 8; j++) {
            int col = bn + ((j < 4) ? (tx * 4 + j) : (64 + tx * 4 + (j - 4)));
            C[(size_t)row * N + col] = acc[i][j];
        }
    }
}

// ---------------------------------------------------------------------------
// RoPE in-place on Q and K heads of qkv [B*T, 48, 64].
// ---------------------------------------------------------------------------
__global__ __launch_bounds__(256) void rope_kernel(float* __restrict__ qkv,
                                                   const float* __restrict__ cos_t,
                                                   const float* __restrict__ sin_t)
{
    int idx = blockIdx.x * blockDim.x + threadIdx.x;
    int half = idx & 31;
    int rest = idx >> 5;
    int head = rest & 31;     // Q heads 0-15, K heads 16-31
    int bt   = rest >> 5;
    int t    = bt & (TT - 1);
    float c = cos_t[t * 64 + half];
    float s = sin_t[t * 64 + half];
    size_t base = ((size_t)bt * 48 + head) * 64;
    float x1 = qkv[base + half];
    float x2 = qkv[base + 32 + half];
    qkv[base + half]      = x1 * c - x2 * s;
    qkv[base + 32 + half] = x2 * c + x1 * s;
}

// ---------------------------------------------------------------------------
// Tensor-core flash attention (tf32x3, m16n8k8).
// Block = (q-tile 64, head, batch), 4 warps x 16 rows, Bc=64, D=64.
// ---------------------------------------------------------------------------
#define QP 68   // pad for Qs/Ks/Ps
#define VP 72   // pad for Vs

__device__ __forceinline__ unsigned f2tf(float x) {
    unsigned u; asm("cvt.rna.tf32.f32 %0, %1;" : "=r"(u) : "f"(x)); return u;
}
__device__ __forceinline__ void split2(float x, unsigned &hi, unsigned &lo) {
    unsigned h_ = f2tf(x);
    lo = f2tf(x - __uint_as_float(h_));
    hi = h_;
}
__device__ __forceinline__ void mma8(float* c,
                                     unsigned a0, unsigned a1, unsigned a2, unsigned a3,
                                     unsigned b0, unsigned b1)
{
    asm volatile(
        "mma.sync.aligned.m16n8k8.row.col.f32.tf32.tf32.f32 "
        "{%0,%1,%2,%3}, {%4,%5,%6,%7}, {%8,%9}, {%0,%1,%2,%3};\n"
        : "+f"(c[0]), "+f"(c[1]), "+f"(c[2]), "+f"(c[3])
        : "r"(a0), "r"(a1), "r"(a2), "r"(a3), "r"(b0), "r"(b1));
}
__device__ __forceinline__ void mma3(float* c, const unsigned* ah, const unsigned* al,
                                     unsigned bh0, unsigned bh1, unsigned bl0, unsigned bl1)
{
    mma8(c, ah[0], ah[1], ah[2], ah[3], bh0, bh1);
    mma8(c, ah[0], ah[1], ah[2], ah[3], bl0, bl1);
    mma8(c, al[0], al[1], al[2], al[3], bh0, bh1);
}

__global__ __launch_bounds__(128) void flash_attn_tc(const float* __restrict__ qkv,
                                                     float* __restrict__ ctx)
{
    extern __shared__ float sm[];
    float* Qs = sm;                 // [64][QP]
    float* Ks = Qs + 64 * QP;       // [64][QP]
    float* Vs = Ks + 64 * QP;       // [64][VP]
    float* Ps = Vs + 64 * VP;       // [64][QP]

    const int qt = blockIdx.x;
    const int h  = blockIdx.y;
    const int b  = blockIdx.z;
    const int tid  = threadIdx.x;
    const int wid  = tid >> 5;
    const int lane = tid & 31;
    const int g  = lane >> 2;       // 0..7
    const int t4 = lane & 3;        // 0..3
    const int wrow = wid * 16;

    // Load Q tile (scaled by 1/sqrt(D)=0.125), float4
#pragma unroll
    for (int i = 0; i < 8; i++) {
        int e = i * 128 + tid;      // 0..1023 float4 slots
        int r = e >> 4;
        int dc = (e & 15) * 4;
        float4 q4 = *(const float4*)&qkv[(((size_t)(b * TT + qt * 64 + r)) * 48 + h) * 64 + dc];
        Qs[r * QP + dc + 0] = q4.x * 0.125f;
        Qs[r * QP + dc + 1] = q4.y * 0.125f;
        Qs[r * QP + dc + 2] = q4.z * 0.125f;
        Qs[r * QP + dc + 3] = q4.w * 0.125f;
    }

    float m0 = -1e30f, m1 = -1e30f, l0 = 0.f, l1 = 0.f;
    float o[8][4];
#pragma unroll
    for (int nt = 0; nt < 8; nt++)
#pragma unroll
        for (int j = 0; j < 4; j++) o[nt][j] = 0.f;

    for (int kt = 0; kt <= qt; kt++) {
        // Load K, V tiles
#pragma unroll
        for (int i = 0; i < 8; i++) {
            int e = i * 128 + tid;
            int r = e >> 4;
            int dc = (e & 15) * 4;
            size_t baseK = (((size_t)(b * TT + kt * 64 + r)) * 48 + NH + h) * 64 + dc;
            float4 k4 = *(const float4*)&qkv[baseK];
            float4 v4 = *(const float4*)&qkv[baseK + NH * 64];
            Ks[r * QP + dc + 0] = k4.x; Ks[r * QP + dc + 1] = k4.y;
            Ks[r * QP + dc + 2] = k4.z; Ks[r * QP + dc + 3] = k4.w;
            Vs[r * VP + dc + 0] = v4.x; Vs[r * VP + dc + 1] = v4.y;
            Vs[r * VP + dc + 2] = v4.z; Vs[r * VP + dc + 3] = v4.w;
        }
        __syncthreads();

        // S = Q @ K^T : per-warp 16x64 in 8 n-tiles
        float s[8][4];
#pragma unroll
        for (int nt = 0; nt < 8; nt++)
#pragma unroll
            for (int j = 0; j < 4; j++) s[nt][j] = 0.f;

#pragma unroll
        for (int ks = 0; ks < 8; ks++) {
            unsigned ah[4], al[4];
            split2(Qs[(wrow + g    ) * QP + ks * 8 + t4    ], ah[0], al[0]);
            split2(Qs[(wrow + g + 8) * QP + ks * 8 + t4    ], ah[1], al[1]);
            split2(Qs[(wrow + g    ) * QP + ks * 8 + t4 + 4], ah[2], al[2]);
            split2(Qs[(wrow + g + 8) * QP + ks * 8 + t4 + 4], ah[3], al[3]);
#pragma unroll
            for (int nt = 0; nt < 8; nt++) {
                unsigned bh0, bl0, bh1, bl1;
                split2(Ks[(nt * 8 + g) * QP + ks * 8 + t4    ], bh0, bl0);
                split2(Ks[(nt * 8 + g) * QP + ks * 8 + t4 + 4], bh1, bl1);
                mma3(s[nt], ah, al, bh0, bh1, bl0, bl1);
            }
        }

        // Causal mask on diagonal tile
        if (kt == qt) {
            int r0 = wrow + g, r1 = wrow + g + 8;
#pragma unroll
            for (int nt = 0; nt < 8; nt++) {
                int c0 = nt * 8 + 2 * t4, c1 = c0 + 1;
                if (c0 > r0) s[nt][0] = -1e30f;
                if (c1 > r0) s[nt][1] = -1e30f;
                if (c0 > r1) s[nt][2] = -1e30f;
                if (c1 > r1) s[nt][3] = -1e30f;
            }
        }

        // Row max (registers + quad shfl)
        float mx0 = -1e30f, mx1 = -1e30f;
#pragma unroll
        for (int nt = 0; nt < 8; nt++) {
            mx0 = fmaxf(mx0, fmaxf(s[nt][0], s[nt][1]));
            mx1 = fmaxf(mx1, fmaxf(s[nt][2], s[nt][3]));
        }
        mx0 = fmaxf(mx0, __shfl_xor_sync(0xffffffffu, mx0, 1));
        mx0 = fmaxf(mx0, __shfl_xor_sync(0xffffffffu, mx0, 2));
        mx1 = fmaxf(mx1, __shfl_xor_sync(0xffffffffu, mx1, 1));
        mx1 = fmaxf(mx1, __shfl_xor_sync(0xffffffffu, mx1, 2));

        float mn0 = fmaxf(m0, mx0), mn1 = fmaxf(m1, mx1);
        float alpha0 = __expf(m0 - mn0), alpha1 = __expf(m1 - mn1);
        m0 = mn0; m1 = mn1;

        float sum0 = 0.f, sum1 = 0.f;
#pragma unroll
        for (int nt = 0; nt < 8; nt++) {
            s[nt][0] = __expf(s[nt][0] - mn0);
            s[nt][1] = __expf(s[nt][1] - mn0);
            s[nt][2] = __expf(s[nt][2] - mn1);
            s[nt][3] = __expf(s[nt][3] - mn1);
            sum0 += s[nt][0] + s[nt][1];
            sum1 += s[nt][2] + s[nt][3];
            // store P to smem (fp32, split at load)
            *(float2*)&Ps[(wrow + g    ) * QP + nt * 8 + 2 * t4] = make_float2(s[nt][0], s[nt][1]);
            *(float2*)&Ps[(wrow + g + 8) * QP + nt * 8 + 2 * t4] = make_float2(s[nt][2], s[nt][3]);
        }
        sum0 += __shfl_xor_sync(0xffffffffu, sum0, 1);
        sum0 += __shfl_xor_sync(0xffffffffu, sum0, 2);
        sum1 += __shfl_xor_sync(0xffffffffu, sum1, 1);
        sum1 += __shfl_xor_sync(0xffffffffu, sum1, 2);
        l0 = l0 * alpha0 + sum0;
        l1 = l1 * alpha1 + sum1;

        // Rescale O accumulators
#pragma unroll
        for (int nt = 0; nt < 8; nt++) {
            o[nt][0] *= alpha0; o[nt][1] *= alpha0;
            o[nt][2] *= alpha1; o[nt][3] *= alpha1;
        }
        __syncwarp();

        // O += P @ V
#pragma unroll
        for (int ks = 0; ks < 8; ks++) {
            unsigned ah[4], al[4];
            split2(Ps[(wrow + g    ) * QP + ks * 8 + t4    ], ah[0], al[0]);
            split2(Ps[(wrow + g + 8) * QP + ks * 8 + t4    ], ah[1], al[1]);
            split2(Ps[(wrow + g    ) * QP + ks * 8 + t4 + 4], ah[2], al[2]);
            split2(Ps[(wrow + g + 8) * QP + ks * 8 + t4 + 4], ah[3], al[3]);
#pragma unroll
            for (int nt = 0; nt < 8; nt++) {
                unsigned bh0, bl0, bh1, bl1;
                split2(Vs[(ks * 8 + t4    ) * VP + nt * 8 + g], bh0, bl0);
                split2(Vs[(ks * 8 + t4 + 4) * VP + nt * 8 + g], bh1, bl1);
                mma3(o[nt], ah, al, bh0, bh1, bl0, bl1);
            }
        }
        __syncthreads();
    }

    // Epilogue: normalize and write ctx [B*T, H*D]
    float inv0 = 1.f / l0, inv1 = 1.f / l1;
    int row0 = qt * 64 + wrow + g;
    int row1 = row0 + 8;
    size_t base0 = ((size_t)(b * TT + row0)) * HIDDEN + h * 64;
    size_t base1 = ((size_t)(b * TT + row1)) * HIDDEN + h * 64;
#pragma unroll
    for (int nt = 0; nt < 8; nt++) {
        int c = nt * 8 + 2 * t4;
        *(float2*)&ctx[base0 + c] = make_float2(o[nt][0] * inv0, o[nt][1] * inv0);
        *(float2*)&ctx[base1 + c] = make_float2(o[nt][2] * inv1, o[nt][3] * inv1);
    }
}

// ---------------------------------------------------------------------------
extern "C" void kernel_launch(void* const* d_in, const int* in_sizes, int n_in,
                              void* d_out, int out_size)
{
    const float* hs    = (const float*)d_in[0];
    const float* cos_t = (const float*)d_in[1];
    const float* sin_t = (const float*)d_in[2];
    const float* wqkv  = (const float*)d_in[3];
    const float* wo    = (const float*)d_in[4];
    float* out = (float*)d_out;

    float* qkv = nullptr;
    float* ctx = nullptr;
    cudaGetSymbolAddress((void**)&qkv, g_qkv);
    cudaGetSymbolAddress((void**)&ctx, g_ctx);

    // 1) QKV = hs @ wqkv^T
    sgemm_nt<<<dim3(QKV_O / 128, MROWS / 128), 256>>>(hs, wqkv, qkv, MROWS, QKV_O, HIDDEN);

    // 2) RoPE
    rope_kernel<<<(BB * TT * 32 * 32) / 256, 256>>>(qkv, cos_t, sin_t);

    // 3) Flash attention (tensor cores, tf32x3)
    const int smem = (64 * QP * 3 + 64 * VP) * (int)sizeof(float);
    cudaFuncSetAttribute(flash_attn_tc, cudaFuncAttributeMaxDynamicSharedMemorySize, smem);
    flash_attn_tc<<<dim3(TT / 64, NH, BB), 128, smem>>>(qkv, ctx);

    // 4) out = ctx @ wo^T
    sgemm_nt<<<dim3(HIDDEN / 128, MROWS / 128), 256>>>(ctx, wo, out, MROWS, HIDDEN, HIDDEN);
}

// round 4
// speedup vs baseline: 1.9665x; 1.9665x over previous
#include <cuda_runtime.h>
#include <cuda_bf16.h>
#include <cstdint>
#include <math.h>

#define BB 2
#define TT 2048
#define HIDDEN 1024
#define NH 16
#define QKV_O 3072   // (16 + 2*16) * 64
#define MROWS (BB*TT) // 4096

// Scratch (allocation-free rule: __device__ globals)
__device__ float g_qkv[(size_t)MROWS * QKV_O];   // [B*T, 3072]
__device__ float g_ctx[(size_t)MROWS * HIDDEN];  // [B*T, 1024]

// ===========================================================================
// Helpers
// ===========================================================================
__device__ __forceinline__ uint32_t smem_to_u32(const void* p) {
    uint32_t a;
    asm("{ .reg .u64 t; cvta.to.shared.u64 t, %1; cvt.u32.u64 %0, t; }" : "=r"(a) : "l"(p));
    return a;
}
__device__ __forceinline__ void ldsm4(unsigned* r, uint32_t addr) {
    asm volatile("ldmatrix.sync.aligned.m8n8.x4.shared.b16 {%0,%1,%2,%3}, [%4];"
                 : "=r"(r[0]), "=r"(r[1]), "=r"(r[2]), "=r"(r[3]) : "r"(addr));
}
__device__ __forceinline__ void mma_bf16(float* c, const unsigned* a, unsigned b0, unsigned b1) {
    asm volatile("mma.sync.aligned.m16n8k16.row.col.f32.bf16.bf16.f32 "
                 "{%0,%1,%2,%3}, {%4,%5,%6,%7}, {%8,%9}, {%0,%1,%2,%3};"
                 : "+f"(c[0]), "+f"(c[1]), "+f"(c[2]), "+f"(c[3])
                 : "r"(a[0]), "r"(a[1]), "r"(a[2]), "r"(a[3]), "r"(b0), "r"(b1));
}
__device__ __forceinline__ void split4(float4 v, uint2& hi, uint2& lo)
{
    __nv_bfloat16 h0 = __float2bfloat16_rn(v.x);
    __nv_bfloat16 h1 = __float2bfloat16_rn(v.y);
    __nv_bfloat16 h2 = __float2bfloat16_rn(v.z);
    __nv_bfloat16 h3 = __float2bfloat16_rn(v.w);
    __nv_bfloat16 l0 = __float2bfloat16_rn(v.x - __bfloat162float(h0));
    __nv_bfloat16 l1 = __float2bfloat16_rn(v.y - __bfloat162float(h1));
    __nv_bfloat16 l2 = __float2bfloat16_rn(v.z - __bfloat162float(h2));
    __nv_bfloat16 l3 = __float2bfloat16_rn(v.w - __bfloat162float(h3));
    __nv_bfloat162 hp0(h0, h1), hp1(h2, h3), lp0(l0, l1), lp1(l2, l3);
    hi.x = *(uint32_t*)&hp0; hi.y = *(uint32_t*)&hp1;
    lo.x = *(uint32_t*)&lp0; lo.y = *(uint32_t*)&lp1;
}

// ===========================================================================
// bf16x3 HMMA GEMM: C[M,N] = A[M,K] * B[N,K]^T  (fp32 in/out), K%32==0,
// M,N%128==0. 128x128 block tile, BK=32, 8 warps (64x32 each).
// ===========================================================================
#define SA 40                      // smem row stride in halves (80 B)
#define T_HALVES (128 * SA)        // one bf16 tile

__global__ __launch_bounds__(256) void gemm_mma(const float* __restrict__ A,
                                                const float* __restrict__ Bm,
                                                float* __restrict__ C,
                                                int M, int N, int K)
{
    __shared__ __nv_bfloat16 sh[4 * T_HALVES];   // Ah | Al | Bh | Bl  (40 KB)
    const uint32_t sbase = smem_to_u32(sh);
    const uint32_t OFF_AL = T_HALVES * 2;        // byte offsets
    const uint32_t OFF_BH = T_HALVES * 4;
    const uint32_t OFF_BL = T_HALVES * 6;

    const int tid  = threadIdx.x;
    const int wid  = tid >> 5;
    const int lane = tid & 31;
    const int warp_m = wid >> 2;      // 0..1
    const int warp_n = wid & 3;       // 0..3
    const int bm = blockIdx.y * 128;
    const int bn = blockIdx.x * 128;
    const int lj = lane & 7;
    const int li = lane >> 3;

    float c[4][4][4];
#pragma unroll
    for (int mt = 0; mt < 4; mt++)
#pragma unroll
        for (int nt = 0; nt < 4; nt++)
#pragma unroll
            for (int j = 0; j < 4; j++) c[mt][nt][j] = 0.f;

    // ldmatrix address components (bytes)
    const int a_row_base = warp_m * 64 + lj + ((li & 1) << 3);
    const int a_col_base = (li >> 1) << 3;
    const int b_row = warp_n * 32 + li * 8 + lj;

    const int nchunks = K >> 5;
    for (int ch = 0; ch < nchunks; ch++) {
        // ---- load 128x32 fp32 of A and B, split to bf16 hi/lo in smem ----
        const float* Ap = A + (size_t)bm * K + ch * 32;
        const float* Bp = Bm + (size_t)bn * K + ch * 32;
#pragma unroll
        for (int i = 0; i < 4; i++) {
            int e = i * 256 + tid;          // 0..1023 float4 slots
            int r  = e >> 3;
            int c4 = (e & 7) << 2;
            uint32_t so = (uint32_t)(r * SA + c4) * 2;
            uint2 h, l;
            split4(*(const float4*)&Ap[(size_t)r * K + c4], h, l);
            *(uint2*)((char*)sh + so) = h;
            *(uint2*)((char*)sh + OFF_AL + so) = l;
            split4(*(const float4*)&Bp[(size_t)r * K + c4], h, l);
            *(uint2*)((char*)sh + OFF_BH + so) = h;
            *(uint2*)((char*)sh + OFF_BL + so) = l;
        }
        __syncthreads();

        // ---- 2 x k16 steps of HMMA ----
#pragma unroll
        for (int ks = 0; ks < 2; ks++) {
            const int k0 = ks * 16;
            unsigned bh[2][4], bl[2][4];
#pragma unroll
            for (int kh = 0; kh < 2; kh++) {
                uint32_t ba = sbase + (uint32_t)(b_row * SA + k0 + kh * 8) * 2;
                ldsm4(bh[kh], OFF_BH + ba);
                ldsm4(bl[kh], OFF_BL + ba);
            }
#pragma unroll
            for (int mt = 0; mt < 4; mt++) {
                unsigned ah[4], al[4];
                uint32_t aa = sbase + (uint32_t)((a_row_base + mt * 16) * SA + k0 + a_col_base) * 2;
                ldsm4(ah, aa);
                ldsm4(al, OFF_AL + aa);
#pragma unroll
                for (int nt = 0; nt < 4; nt++) {
                    mma_bf16(c[mt][nt], ah, bh[0][nt], bh[1][nt]);
                    mma_bf16(c[mt][nt], ah, bl[0][nt], bl[1][nt]);
                    mma_bf16(c[mt][nt], al, bh[0][nt], bh[1][nt]);
                }
            }
        }
        __syncthreads();
    }

    // ---- epilogue ----
    const int q  = lane >> 2;
    const int t4 = lane & 3;
#pragma unroll
    for (int mt = 0; mt < 4; mt++) {
        int row0 = bm + warp_m * 64 + mt * 16 + q;
#pragma unroll
        for (int nt = 0; nt < 4; nt++) {
            int col = bn + warp_n * 32 + nt * 8 + 2 * t4;
            *(float2*)&C[(size_t)row0 * N + col] =
                make_float2(c[mt][nt][0], c[mt][nt][1]);
            *(float2*)&C[(size_t)(row0 + 8) * N + col] =
                make_float2(c[mt][nt][2], c[mt][nt][3]);
        }
    }
}

// ---------------------------------------------------------------------------
// RoPE in-place on Q and K heads of qkv [B*T, 48, 64].
// ---------------------------------------------------------------------------
__global__ __launch_bounds__(256) void rope_kernel(float* __restrict__ qkv,
                                                   const float* __restrict__ cos_t,
                                                   const float* __restrict__ sin_t)
{
    int idx = blockIdx.x * blockDim.x + threadIdx.x;
    int half = idx & 31;
    int rest = idx >> 5;
    int head = rest & 31;     // Q heads 0-15, K heads 16-31
    int bt   = rest >> 5;
    int t    = bt & (TT - 1);
    float c = cos_t[t * 64 + half];
    float s = sin_t[t * 64 + half];
    size_t base = ((size_t)bt * 48 + head) * 64;
    float x1 = qkv[base + half];
    float x2 = qkv[base + 32 + half];
    qkv[base + half]      = x1 * c - x2 * s;
    qkv[base + 32 + half] = x2 * c + x1 * s;
}

// ---------------------------------------------------------------------------
// fp32 SIMT flash attention (round-1 version, known-good).
// ---------------------------------------------------------------------------
#define LD 65
__global__ __launch_bounds__(256) void flash_attn(const float* __restrict__ qkv,
                                                  float* __restrict__ ctx)
{
    extern __shared__ float sm[];
    float* Qs = sm;
    float* Ks = Qs + 64 * LD;
    float* Vs = Ks + 64 * LD;
    float* Ps = Vs + 64 * LD;

    const int qt = blockIdx.x;
    const int h  = blockIdx.y;
    const int b  = blockIdx.z;
    const int tid = threadIdx.x;
    const int rg = tid >> 4;
    const int cg = tid & 15;

    const float scale = 0.125f;
#pragma unroll
    for (int i = 0; i < 16; i++) {
        int e = i * 256 + tid;
        int r = e >> 6, d = e & 63;
        int t = qt * 64 + r;
        Qs[r * LD + d] = qkv[(((size_t)(b * TT + t)) * 48 + h) * 64 + d] * scale;
    }

    float m[4]   = {-1e30f, -1e30f, -1e30f, -1e30f};
    float l[4]   = {0.f, 0.f, 0.f, 0.f};
    float o[4][4];
#pragma unroll
    for (int i = 0; i < 4; i++)
#pragma unroll
        for (int j = 0; j < 4; j++) o[i][j] = 0.f;

    __syncthreads();

    for (int kt = 0; kt <= qt; kt++) {
#pragma unroll
        for (int i = 0; i < 16; i++) {
            int e = i * 256 + tid;
            int r = e >> 6, d = e & 63;
            int t = kt * 64 + r;
            size_t baseK = (((size_t)(b * TT + t)) * 48 + NH + h) * 64 + d;
            Ks[r * LD + d] = qkv[baseK];
            Vs[r * LD + d] = qkv[baseK + NH * 64];
        }
        __syncthreads();

        float s[4][4];
#pragma unroll
        for (int i = 0; i < 4; i++)
#pragma unroll
            for (int j = 0; j < 4; j++) s[i][j] = 0.f;

        for (int d = 0; d < 64; d++) {
            float a0 = Qs[(rg * 4 + 0) * LD + d];
            float a1 = Qs[(rg * 4 + 1) * LD + d];
            float a2 = Qs[(rg * 4 + 2) * LD + d];
            float a3 = Qs[(rg * 4 + 3) * LD + d];
            float b0 = Ks[(cg * 4 + 0) * LD + d];
            float b1 = Ks[(cg * 4 + 1) * LD + d];
            float b2 = Ks[(cg * 4 + 2) * LD + d];
            float b3 = Ks[(cg * 4 + 3) * LD + d];
            s[0][0] += a0 * b0; s[0][1] += a0 * b1; s[0][2] += a0 * b2; s[0][3] += a0 * b3;
            s[1][0] += a1 * b0; s[1][1] += a1 * b1; s[1][2] += a1 * b2; s[1][3] += a1 * b3;
            s[2][0] += a2 * b0; s[2][1] += a2 * b1; s[2][2] += a2 * b2; s[2][3] += a2 * b3;
            s[3][0] += a3 * b0; s[3][1] += a3 * b1; s[3][2] += a3 * b2; s[3][3] += a3 * b3;
        }

        if (kt == qt) {
#pragma unroll
            for (int i = 0; i < 4; i++)
#pragma unroll
                for (int j = 0; j < 4; j++)
                    if (cg * 4 + j > rg * 4 + i) s[i][j] = -1e30f;
        }

        float mx[4];
#pragma unroll
        for (int i = 0; i < 4; i++) {
            float v = fmaxf(fmaxf(s[i][0], s[i][1]), fmaxf(s[i][2], s[i][3]));
#pragma unroll
            for (int off = 1; off < 16; off <<= 1)
                v = fmaxf(v, __shfl_xor_sync(0xffffffffu, v, off));
            mx[i] = v;
        }

        float alpha[4], rs[4];
#pragma unroll
        for (int i = 0; i < 4; i++) {
            float mn = fmaxf(m[i], mx[i]);
            alpha[i] = __expf(m[i] - mn);
            m[i] = mn;
            float acc = 0.f;
#pragma unroll
            for (int j = 0; j < 4; j++) {
                float p = __expf(s[i][j] - mn);
                s[i][j] = p;
                acc += p;
            }
#pragma unroll
            for (int off = 1; off < 16; off <<= 1)
                acc += __shfl_xor_sync(0xffffffffu, acc, off);
            rs[i] = acc;
        }
#pragma unroll
        for (int i = 0; i < 4; i++) {
            l[i] = l[i] * alpha[i] + rs[i];
#pragma unroll
            for (int j = 0; j < 4; j++) o[i][j] *= alpha[i];
#pragma unroll
            for (int j = 0; j < 4; j++)
                Ps[(rg * 4 + i) * LD + cg * 4 + j] = s[i][j];
        }
        __syncwarp();

        for (int c = 0; c < 64; c++) {
            float p0 = Ps[(rg * 4 + 0) * LD + c];
            float p1 = Ps[(rg * 4 + 1) * LD + c];
            float p2 = Ps[(rg * 4 + 2) * LD + c];
            float p3 = Ps[(rg * 4 + 3) * LD + c];
            float v0 = Vs[c * LD + cg * 4 + 0];
            float v1 = Vs[c * LD + cg * 4 + 1];
            float v2 = Vs[c * LD + cg * 4 + 2];
            float v3 = Vs[c * LD + cg * 4 + 3];
            o[0][0] += p0 * v0; o[0][1] += p0 * v1; o[0][2] += p0 * v2; o[0][3] += p0 * v3;
            o[1][0] += p1 * v0; o[1][1] += p1 * v1; o[1][2] += p1 * v2; o[1][3] += p1 * v3;
            o[2][0] += p2 * v0; o[2][1] += p2 * v1; o[2][2] += p2 * v2; o[2][3] += p2 * v3;
            o[3][0] += p3 * v0; o[3][1] += p3 * v1; o[3][2] += p3 * v2; o[3][3] += p3 * v3;
        }
        __syncthreads();
    }

#pragma unroll
    for (int i = 0; i < 4; i++) {
        float inv = 1.f / l[i];
        int t = qt * 64 + rg * 4 + i;
        size_t base = ((size_t)(b * TT + t)) * HIDDEN + h * 64;
#pragma unroll
        for (int j = 0; j < 4; j++)
            ctx[base + cg * 4 + j] = o[i][j] * inv;
    }
}

// ---------------------------------------------------------------------------
extern "C" void kernel_launch(void* const* d_in, const int* in_sizes, int n_in,
                              void* d_out, int out_size)
{
    const float* hs    = (const float*)d_in[0];
    const float* cos_t = (const float*)d_in[1];
    const float* sin_t = (const float*)d_in[2];
    const float* wqkv  = (const float*)d_in[3];
    const float* wo    = (const float*)d_in[4];
    float* out = (float*)d_out;

    float* qkv = nullptr;
    float* ctx = nullptr;
    cudaGetSymbolAddress((void**)&qkv, g_qkv);
    cudaGetSymbolAddress((void**)&ctx, g_ctx);

    // 1) QKV = hs @ wqkv^T  [4096, 3072]
    gemm_mma<<<dim3(QKV_O / 128, MROWS / 128), 256>>>(hs, wqkv, qkv, MROWS, QKV_O, HIDDEN);

    // 2) RoPE
    rope_kernel<<<(BB * TT * 32 * 32) / 256, 256>>>(qkv, cos_t, sin_t);

    // 3) Flash attention (SIMT fp32)
    const int fa_smem = 4 * 64 * LD * (int)sizeof(float);
    cudaFuncSetAttribute(flash_attn, cudaFuncAttributeMaxDynamicSharedMemorySize, fa_smem);
    flash_attn<<<dim3(TT / 64, NH, BB), 256, fa_smem>>>(qkv, ctx);

    // 4) out = ctx @ wo^T  [4096, 1024]
    gemm_mma<<<dim3(HIDDEN / 128, MROWS / 128), 256>>>(ctx, wo, out, MROWS, HIDDEN, HIDDEN);
}

// round 6
// speedup vs baseline: 3.4969x; 1.7782x over previous
#include <cuda_runtime.h>
#include <cuda_bf16.h>
#include <cstdint>
#include <math.h>

#define BB 2
#define TT 2048
#define HIDDEN 1024
#define NH 16
#define QKV_O 3072   // (16 + 2*16) * 64
#define MROWS (BB*TT) // 4096

__device__ float g_qkv[(size_t)MROWS * QKV_O];   // [B*T, 3072]
__device__ float g_ctx[(size_t)MROWS * HIDDEN];  // [B*T, 1024]

// ===========================================================================
// Helpers
// ===========================================================================
__device__ __forceinline__ uint32_t smem_to_u32(const void* p) {
    uint32_t a;
    asm("{ .reg .u64 t; cvta.to.shared.u64 t, %1; cvt.u32.u64 %0, t; }" : "=r"(a) : "l"(p));
    return a;
}
__device__ __forceinline__ void ldsm4(unsigned* r, uint32_t addr) {
    asm volatile("ldmatrix.sync.aligned.m8n8.x4.shared.b16 {%0,%1,%2,%3}, [%4];"
                 : "=r"(r[0]), "=r"(r[1]), "=r"(r[2]), "=r"(r[3]) : "r"(addr));
}
__device__ __forceinline__ void ldsm4t(unsigned* r, uint32_t addr) {
    asm volatile("ldmatrix.sync.aligned.m8n8.x4.trans.shared.b16 {%0,%1,%2,%3}, [%4];"
                 : "=r"(r[0]), "=r"(r[1]), "=r"(r[2]), "=r"(r[3]) : "r"(addr));
}
__device__ __forceinline__ void mma_bf16(float* c, const unsigned* a, unsigned b0, unsigned b1) {
    asm volatile("mma.sync.aligned.m16n8k16.row.col.f32.bf16.bf16.f32 "
                 "{%0,%1,%2,%3}, {%4,%5,%6,%7}, {%8,%9}, {%0,%1,%2,%3};"
                 : "+f"(c[0]), "+f"(c[1]), "+f"(c[2]), "+f"(c[3])
                 : "r"(a[0]), "r"(a[1]), "r"(a[2]), "r"(a[3]), "r"(b0), "r"(b1));
}
__device__ __forceinline__ void split4(float4 v, uint2& hi, uint2& lo)
{
    __nv_bfloat16 h0 = __float2bfloat16_rn(v.x);
    __nv_bfloat16 h1 = __float2bfloat16_rn(v.y);
    __nv_bfloat16 h2 = __float2bfloat16_rn(v.z);
    __nv_bfloat16 h3 = __float2bfloat16_rn(v.w);
    __nv_bfloat16 l0 = __float2bfloat16_rn(v.x - __bfloat162float(h0));
    __nv_bfloat16 l1 = __float2bfloat16_rn(v.y - __bfloat162float(h1));
    __nv_bfloat16 l2 = __float2bfloat16_rn(v.z - __bfloat162float(h2));
    __nv_bfloat16 l3 = __float2bfloat16_rn(v.w - __bfloat162float(h3));
    __nv_bfloat162 hp0(h0, h1), hp1(h2, h3), lp0(l0, l1), lp1(l2, l3);
    hi.x = *(uint32_t*)&hp0; hi.y = *(uint32_t*)&hp1;
    lo.x = *(uint32_t*)&lp0; lo.y = *(uint32_t*)&lp1;
}
__device__ __forceinline__ unsigned pk(float x, float y) {
    __nv_bfloat162 p(__float2bfloat16_rn(x), __float2bfloat16_rn(y));
    return *(unsigned*)&p;
}

// ===========================================================================
// bf16x3 HMMA GEMM (round-4, proven): C[M,N] = A[M,K] * B[N,K]^T
// ===========================================================================
#define SA 40
#define T_HALVES (128 * SA)

__global__ __launch_bounds__(256) void gemm_mma(const float* __restrict__ A,
                                                const float* __restrict__ Bm,
                                                float* __restrict__ C,
                                                int M, int N, int K)
{
    __shared__ __nv_bfloat16 sh[4 * T_HALVES];
    const uint32_t sbase = smem_to_u32(sh);
    const uint32_t OFF_AL = T_HALVES * 2;
    const uint32_t OFF_BH = T_HALVES * 4;
    const uint32_t OFF_BL = T_HALVES * 6;

    const int tid  = threadIdx.x;
    const int wid  = tid >> 5;
    const int lane = tid & 31;
    const int warp_m = wid >> 2;
    const int warp_n = wid & 3;
    const int bm = blockIdx.y * 128;
    const int bn = blockIdx.x * 128;
    const int lj = lane & 7;
    const int li = lane >> 3;

    float c[4][4][4];
#pragma unroll
    for (int mt = 0; mt < 4; mt++)
#pragma unroll
        for (int nt = 0; nt < 4; nt++)
#pragma unroll
            for (int j = 0; j < 4; j++) c[mt][nt][j] = 0.f;

    const int a_row_base = warp_m * 64 + lj + ((li & 1) << 3);
    const int a_col_base = (li >> 1) << 3;
    const int b_row = warp_n * 32 + li * 8 + lj;

    const int nchunks = K >> 5;
    for (int ch = 0; ch < nchunks; ch++) {
        const float* Ap = A + (size_t)bm * K + ch * 32;
        const float* Bp = Bm + (size_t)bn * K + ch * 32;
#pragma unroll
        for (int i = 0; i < 4; i++) {
            int e = i * 256 + tid;
            int r  = e >> 3;
            int c4 = (e & 7) << 2;
            uint32_t so = (uint32_t)(r * SA + c4) * 2;
            uint2 h, l;
            split4(*(const float4*)&Ap[(size_t)r * K + c4], h, l);
            *(uint2*)((char*)sh + so) = h;
            *(uint2*)((char*)sh + OFF_AL + so) = l;
            split4(*(const float4*)&Bp[(size_t)r * K + c4], h, l);
            *(uint2*)((char*)sh + OFF_BH + so) = h;
            *(uint2*)((char*)sh + OFF_BL + so) = l;
        }
        __syncthreads();

#pragma unroll
        for (int ks = 0; ks < 2; ks++) {
            const int k0 = ks * 16;
            unsigned bh[2][4], bl[2][4];
#pragma unroll
            for (int kh = 0; kh < 2; kh++) {
                uint32_t ba = sbase + (uint32_t)(b_row * SA + k0 + kh * 8) * 2;
                ldsm4(bh[kh], OFF_BH + ba);
                ldsm4(bl[kh], OFF_BL + ba);
            }
#pragma unroll
            for (int mt = 0; mt < 4; mt++) {
                unsigned ah[4], al[4];
                uint32_t aa = sbase + (uint32_t)((a_row_base + mt * 16) * SA + k0 + a_col_base) * 2;
                ldsm4(ah, aa);
                ldsm4(al, OFF_AL + aa);
#pragma unroll
                for (int nt = 0; nt < 4; nt++) {
                    mma_bf16(c[mt][nt], ah, bh[0][nt], bh[1][nt]);
                    mma_bf16(c[mt][nt], ah, bl[0][nt], bl[1][nt]);
                    mma_bf16(c[mt][nt], al, bh[0][nt], bh[1][nt]);
                }
            }
        }
        __syncthreads();
    }

    const int q  = lane >> 2;
    const int t4 = lane & 3;
#pragma unroll
    for (int mt = 0; mt < 4; mt++) {
        int row0 = bm + warp_m * 64 + mt * 16 + q;
#pragma unroll
        for (int nt = 0; nt < 4; nt++) {
            int col = bn + warp_n * 32 + nt * 8 + 2 * t4;
            *(float2*)&C[(size_t)row0 * N + col] =
                make_float2(c[mt][nt][0], c[mt][nt][1]);
            *(float2*)&C[(size_t)(row0 + 8) * N + col] =
                make_float2(c[mt][nt][2], c[mt][nt][3]);
        }
    }
}

// ---------------------------------------------------------------------------
// RoPE in-place on Q and K heads of qkv [B*T, 48, 64].
// ---------------------------------------------------------------------------
__global__ __launch_bounds__(256) void rope_kernel(float* __restrict__ qkv,
                                                   const float* __restrict__ cos_t,
                                                   const float* __restrict__ sin_t)
{
    int idx = blockIdx.x * blockDim.x + threadIdx.x;
    int half = idx & 31;
    int rest = idx >> 5;
    int head = rest & 31;
    int bt   = rest >> 5;
    int t    = bt & (TT - 1);
    float c = cos_t[t * 64 + half];
    float s = sin_t[t * 64 + half];
    size_t base = ((size_t)bt * 48 + head) * 64;
    float x1 = qkv[base + half];
    float x2 = qkv[base + 32 + half];
    qkv[base + half]      = x1 * c - x2 * s;
    qkv[base + 32 + half] = x2 * c + x1 * s;
}

// ===========================================================================
// bf16x3 HMMA flash attention (causal). Block = (64 q-rows, head, batch),
// 4 warps x 16 rows, Bc=64, D=64. FA2 register-resident P.
// Dedicated stride FSA=72 halves (144B rows: 16B-aligned, conflict-free).
// ===========================================================================
#define FSA 72
#define FT (64 * FSA)   // halves per tile

__global__ __launch_bounds__(128) void flash_attn_mma(const float* __restrict__ qkv,
                                                      float* __restrict__ ctx)
{
    extern __shared__ __nv_bfloat16 sh[];   // Qh Ql Kh Kl Vh Vl  (54 KB)
    const uint32_t sbase = smem_to_u32(sh);
    const uint32_t oQl = FT * 2, oKh = FT * 4, oKl = FT * 6, oVh = FT * 8, oVl = FT * 10;

    const int qt = blockIdx.x;
    const int h  = blockIdx.y;
    const int b  = blockIdx.z;
    const int tid  = threadIdx.x;
    const int wid  = tid >> 5;
    const int lane = tid & 31;
    const int lj = lane & 7;
    const int li = lane >> 3;
    const int g  = lane >> 2;
    const int t4 = lane & 3;
    const int wrow = wid * 16;

    // ---- load Q tile (scaled), split hi/lo ----
#pragma unroll
    for (int i = 0; i < 8; i++) {
        int e = i * 128 + tid;              // 1024 float4 slots
        int r = e >> 4;
        int c4 = (e & 15) << 2;
        float4 q4 = *(const float4*)&qkv[(((size_t)(b * TT + qt * 64 + r)) * 48 + h) * 64 + c4];
        q4.x *= 0.125f; q4.y *= 0.125f; q4.z *= 0.125f; q4.w *= 0.125f;
        uint2 hv, lv;
        split4(q4, hv, lv);
        uint32_t so = (uint32_t)(r * FSA + c4) * 2;
        *(uint2*)((char*)sh + so) = hv;
        *(uint2*)((char*)sh + oQl + so) = lv;
    }

    float m0 = -1e30f, m1 = -1e30f, l0 = 0.f, l1 = 0.f;
    float o[8][4];
#pragma unroll
    for (int nt = 0; nt < 8; nt++)
#pragma unroll
        for (int j = 0; j < 4; j++) o[nt][j] = 0.f;

    // ldmatrix address components
    const int a_row = wrow + lj + ((li & 1) << 3);
    const int a_col = (li >> 1) << 3;
    const int b_row = li * 8 + lj;                      // n-rows for K (0..31)
    const int v_row = lj + ((li & 1) << 3);             // k-rows for V
    const int v_col = (lane >> 4) << 3;                 // +0 / +8 n

    __syncthreads();

    for (int kt = 0; kt <= qt; kt++) {
        // ---- load K/V tiles, split hi/lo ----
#pragma unroll
        for (int i = 0; i < 8; i++) {
            int e = i * 128 + tid;
            int r = e >> 4;
            int c4 = (e & 15) << 2;
            size_t baseK = (((size_t)(b * TT + kt * 64 + r)) * 48 + NH + h) * 64 + c4;
            uint32_t so = (uint32_t)(r * FSA + c4) * 2;
            uint2 hv, lv;
            split4(*(const float4*)&qkv[baseK], hv, lv);
            *(uint2*)((char*)sh + oKh + so) = hv;
            *(uint2*)((char*)sh + oKl + so) = lv;
            split4(*(const float4*)&qkv[baseK + NH * 64], hv, lv);
            *(uint2*)((char*)sh + oVh + so) = hv;
            *(uint2*)((char*)sh + oVl + so) = lv;
        }
        __syncthreads();

        // ---- S = Q @ K^T (16x64 per warp), bf16x3 ----
        float s[8][4];
#pragma unroll
        for (int nt = 0; nt < 8; nt++)
#pragma unroll
            for (int j = 0; j < 4; j++) s[nt][j] = 0.f;

#pragma unroll
        for (int ks = 0; ks < 4; ks++) {
            const int k0 = ks * 16;
            unsigned ah[4], al[4];
            uint32_t aa = sbase + (uint32_t)(a_row * FSA + k0 + a_col) * 2;
            ldsm4(ah, aa);
            ldsm4(al, oQl + aa);
#pragma unroll
            for (int nh = 0; nh < 2; nh++) {
                unsigned bh[2][4], bl[2][4];
#pragma unroll
                for (int kh = 0; kh < 2; kh++) {
                    uint32_t ba = sbase + (uint32_t)((b_row + nh * 32) * FSA + k0 + kh * 8) * 2;
                    ldsm4(bh[kh], oKh + ba);
                    ldsm4(bl[kh], oKl + ba);
                }
#pragma unroll
                for (int nt = 0; nt < 4; nt++) {
                    float* sc = s[nh * 4 + nt];
                    mma_bf16(sc, ah, bh[0][nt], bh[1][nt]);
                    mma_bf16(sc, ah, bl[0][nt], bl[1][nt]);
                    mma_bf16(sc, al, bh[0][nt], bh[1][nt]);
                }
            }
        }

        // ---- causal mask (diagonal tile only) ----
        if (kt == qt) {
            int r0 = wrow + g, r1 = r0 + 8;
#pragma unroll
            for (int nt = 0; nt < 8; nt++) {
                int c0 = nt * 8 + 2 * t4, c1 = c0 + 1;
                if (c0 > r0) s[nt][0] = -1e30f;
                if (c1 > r0) s[nt][1] = -1e30f;
                if (c0 > r1) s[nt][2] = -1e30f;
                if (c1 > r1) s[nt][3] = -1e30f;
            }
        }

        // ---- online softmax ----
        float mx0 = -1e30f, mx1 = -1e30f;
#pragma unroll
        for (int nt = 0; nt < 8; nt++) {
            mx0 = fmaxf(mx0, fmaxf(s[nt][0], s[nt][1]));
            mx1 = fmaxf(mx1, fmaxf(s[nt][2], s[nt][3]));
        }
        mx0 = fmaxf(mx0, __shfl_xor_sync(0xffffffffu, mx0, 1));
        mx0 = fmaxf(mx0, __shfl_xor_sync(0xffffffffu, mx0, 2));
        mx1 = fmaxf(mx1, __shfl_xor_sync(0xffffffffu, mx1, 1));
        mx1 = fmaxf(mx1, __shfl_xor_sync(0xffffffffu, mx1, 2));

        float mn0 = fmaxf(m0, mx0), mn1 = fmaxf(m1, mx1);
        float alpha0 = __expf(m0 - mn0), alpha1 = __expf(m1 - mn1);
        m0 = mn0; m1 = mn1;

        float sum0 = 0.f, sum1 = 0.f;
#pragma unroll
        for (int nt = 0; nt < 8; nt++) {
            s[nt][0] = __expf(s[nt][0] - mn0);
            s[nt][1] = __expf(s[nt][1] - mn0);
            s[nt][2] = __expf(s[nt][2] - mn1);
            s[nt][3] = __expf(s[nt][3] - mn1);
            sum0 += s[nt][0] + s[nt][1];
            sum1 += s[nt][2] + s[nt][3];
        }
        sum0 += __shfl_xor_sync(0xffffffffu, sum0, 1);
        sum0 += __shfl_xor_sync(0xffffffffu, sum0, 2);
        sum1 += __shfl_xor_sync(0xffffffffu, sum1, 1);
        sum1 += __shfl_xor_sync(0xffffffffu, sum1, 2);
        l0 = l0 * alpha0 + sum0;
        l1 = l1 * alpha1 + sum1;

#pragma unroll
        for (int nt = 0; nt < 8; nt++) {
            o[nt][0] *= alpha0; o[nt][1] *= alpha0;
            o[nt][2] *= alpha1; o[nt][3] *= alpha1;
        }

        // ---- O += P @ V (P register-resident, bf16x3) ----
#pragma unroll
        for (int ks = 0; ks < 4; ks++) {
            const int k0 = ks * 16;
            unsigned ah[4], al[4];
            {
                float* p0 = s[2 * ks];
                float* p1 = s[2 * ks + 1];
                ah[0] = pk(p0[0], p0[1]);
                ah[1] = pk(p0[2], p0[3]);
                ah[2] = pk(p1[0], p1[1]);
                ah[3] = pk(p1[2], p1[3]);
                float h00 = __bfloat162float(__float2bfloat16_rn(p0[0]));
                float h01 = __bfloat162float(__float2bfloat16_rn(p0[1]));
                float h02 = __bfloat162float(__float2bfloat16_rn(p0[2]));
                float h03 = __bfloat162float(__float2bfloat16_rn(p0[3]));
                float h10 = __bfloat162float(__float2bfloat16_rn(p1[0]));
                float h11 = __bfloat162float(__float2bfloat16_rn(p1[1]));
                float h12 = __bfloat162float(__float2bfloat16_rn(p1[2]));
                float h13 = __bfloat162float(__float2bfloat16_rn(p1[3]));
                al[0] = pk(p0[0] - h00, p0[1] - h01);
                al[1] = pk(p0[2] - h02, p0[3] - h03);
                al[2] = pk(p1[0] - h10, p1[1] - h11);
                al[3] = pk(p1[2] - h12, p1[3] - h13);
            }
#pragma unroll
            for (int nh = 0; nh < 4; nh++) {
                uint32_t va = sbase + (uint32_t)((k0 + v_row) * FSA + nh * 16 + v_col) * 2;
                unsigned vh[4], vl[4];
                ldsm4t(vh, oVh + va);
                ldsm4t(vl, oVl + va);
                float* o0 = o[nh * 2];
                float* o1 = o[nh * 2 + 1];
                mma_bf16(o0, ah, vh[0], vh[1]);
                mma_bf16(o0, ah, vl[0], vl[1]);
                mma_bf16(o0, al, vh[0], vh[1]);
                mma_bf16(o1, ah, vh[2], vh[3]);
                mma_bf16(o1, ah, vl[2], vl[3]);
                mma_bf16(o1, al, vh[2], vh[3]);
            }
        }
        __syncthreads();
    }

    // ---- epilogue: normalize, write ctx [B*T, H*D] ----
    float inv0 = 1.f / l0, inv1 = 1.f / l1;
    int row0 = qt * 64 + wrow + g;
    size_t base0 = ((size_t)(b * TT + row0)) * HIDDEN + h * 64;
    size_t base1 = base0 + 8 * HIDDEN;
#pragma unroll
    for (int nt = 0; nt < 8; nt++) {
        int c = nt * 8 + 2 * t4;
        *(float2*)&ctx[base0 + c] = make_float2(o[nt][0] * inv0, o[nt][1] * inv0);
        *(float2*)&ctx[base1 + c] = make_float2(o[nt][2] * inv1, o[nt][3] * inv1);
    }
}

// ---------------------------------------------------------------------------
extern "C" void kernel_launch(void* const* d_in, const int* in_sizes, int n_in,
                              void* d_out, int out_size)
{
    const float* hs    = (const float*)d_in[0];
    const float* cos_t = (const float*)d_in[1];
    const float* sin_t = (const float*)d_in[2];
    const float* wqkv  = (const float*)d_in[3];
    const float* wo    = (const float*)d_in[4];
    float* out = (float*)d_out;

    float* qkv = nullptr;
    float* ctx = nullptr;
    cudaGetSymbolAddress((void**)&qkv, g_qkv);
    cudaGetSymbolAddress((void**)&ctx, g_ctx);

    // 1) QKV = hs @ wqkv^T  [4096, 3072]
    gemm_mma<<<dim3(QKV_O / 128, MROWS / 128), 256>>>(hs, wqkv, qkv, MROWS, QKV_O, HIDDEN);

    // 2) RoPE
    rope_kernel<<<(BB * TT * 32 * 32) / 256, 256>>>(qkv, cos_t, sin_t);

    // 3) Flash attention (bf16x3 HMMA), 54KB dynamic smem
    const int fa_smem = 6 * FT * (int)sizeof(__nv_bfloat16);
    cudaFuncSetAttribute(flash_attn_mma, cudaFuncAttributeMaxDynamicSharedMemorySize, fa_smem);
    flash_attn_mma<<<dim3(TT / 64, NH, BB), 128, fa_smem>>>(qkv, ctx);

    // 4) out = ctx @ wo^T  [4096, 1024]
    gemm_mma<<<dim3(HIDDEN / 128, MROWS / 128), 256>>>(ctx, wo, out, MROWS, HIDDEN, HIDDEN);
}